// round 9
// baseline (speedup 1.0000x reference)
#include <cuda_runtime.h>
#include <math.h>

#define B 32
#define N 32768
#define D 128
#define CH 128
#define NCH (N / CH)          // 256 chunks
#define NT 256                // threads per chunk CTA
#define NCG 8                 // chunk groups in stage-1 reduce
#define CPG (NCH / NCG)       // 32 chunks per group
#define YSTRIDE (D + 4)       // 132 floats: conflict-free LDS.128 row reads

// scratch (no allocations allowed)
__device__ float g_cmax[B * NCH];        // [B][NCH]
__device__ float g_csum[B * NCH];        // [B][NCH]
__device__ float g_cvec[NCH * B * D];    // [C][B][D] — coalesced stores
__device__ float g_pvec2[B * NCG * D];   // [B][CG][D]

// ---------------------------------------------------------------------------
// K1: fused chunk kernel, 256 threads, 2x8 register tiling.
//  bg = t>>6 (4 groups of 8 b's), tt = t&63.
//  Phase A: thread owns n-rows tt, tt+64; dot[2][8].
//  Phase B: thread owns d-cols tt, tt+64; acc[2][8].
// ---------------------------------------------------------------------------
__global__ __launch_bounds__(NT, 2) void k_chunk(const float* __restrict__ x,
                                                 const float* __restrict__ al,
                                                 const float* __restrict__ y) {
    extern __shared__ float smem[];
    float* ys = smem;                    // CH * YSTRIDE   (67.6 KB)
    float* xs = ys + CH * YSTRIDE;       // B * D          (16 KB)
    float* es = xs + B * D;              // B * CH         (16 KB)
    __shared__ float sA[B], sScale[B], sC[B], cm[B];

    const int t = threadIdx.x;
    const int base = blockIdx.x * CH;
    const int bg = t >> 6;               // 0..3: which 8 b's
    const int tt = t & 63;
    const int bbase = bg * 8;

    // stage y chunk (coalesced float4, padded rows)
    const float4* y4 = reinterpret_cast<const float4*>(y + (size_t)base * D);
    #pragma unroll
    for (int i = t; i < CH * D / 4; i += NT) {
        int row = i >> 5;
        int c4  = i & 31;
        *reinterpret_cast<float4*>(&ys[row * YSTRIDE + c4 * 4]) = y4[i];
    }
    const float4* x4 = reinterpret_cast<const float4*>(x);
    #pragma unroll
    for (int i = t; i < B * D / 4; i += NT)
        reinterpret_cast<float4*>(xs)[i] = x4[i];
    __syncthreads();

    if (t < B) {
        float a = al[t];
        float var = 1.0f - a;
        float x2 = 0.f;
        #pragma unroll 8
        for (int d = 0; d < D; d++) { float v = xs[t * D + d]; x2 = fmaf(v, v, x2); }
        sA[t] = -(0.5f * (float)D * logf(var) + 0.5f / var * x2);
        sScale[t] = sqrtf(a) / var;
        sC[t] = 0.5f * a / var;
    }
    __syncthreads();

    // ---- Phase A: dot[2][8] over d. 10 LDS.128 per iter for 64 FMAs ----
    float dot0[8], dot1[8];
    #pragma unroll
    for (int j = 0; j < 8; j++) { dot0[j] = 0.f; dot1[j] = 0.f; }
    float y2n0 = 0.f, y2n1 = 0.f;

    const float4* yr0 = reinterpret_cast<const float4*>(&ys[tt * YSTRIDE]);
    const float4* yr1 = reinterpret_cast<const float4*>(&ys[(tt + 64) * YSTRIDE]);
    const float4* xs4 = reinterpret_cast<const float4*>(xs);
    #pragma unroll 4
    for (int d4 = 0; d4 < D / 4; d4++) {
        float4 a0 = yr0[d4];
        float4 a1 = yr1[d4];
        y2n0 = fmaf(a0.x, a0.x, fmaf(a0.y, a0.y, fmaf(a0.z, a0.z, fmaf(a0.w, a0.w, y2n0))));
        y2n1 = fmaf(a1.x, a1.x, fmaf(a1.y, a1.y, fmaf(a1.z, a1.z, fmaf(a1.w, a1.w, y2n1))));
        #pragma unroll
        for (int j = 0; j < 8; j++) {
            float4 xv = xs4[(bbase + j) * (D / 4) + d4];   // warp broadcast
            dot0[j] = fmaf(xv.x, a0.x, dot0[j]);
            dot0[j] = fmaf(xv.y, a0.y, dot0[j]);
            dot0[j] = fmaf(xv.z, a0.z, dot0[j]);
            dot0[j] = fmaf(xv.w, a0.w, dot0[j]);
            dot1[j] = fmaf(xv.x, a1.x, dot1[j]);
            dot1[j] = fmaf(xv.y, a1.y, dot1[j]);
            dot1[j] = fmaf(xv.z, a1.z, dot1[j]);
            dot1[j] = fmaf(xv.w, a1.w, dot1[j]);
        }
    }

    // logits -> es (raw)
    #pragma unroll
    for (int j = 0; j < 8; j++) {
        const int b = bbase + j;
        es[b * CH + tt]      = fmaf(sScale[b], dot0[j], sA[b]) - sC[b] * y2n0;
        es[b * CH + tt + 64] = fmaf(sScale[b], dot1[j], sA[b]) - sC[b] * y2n1;
    }
    __syncthreads();

    // max pass: 8 warps, warp w handles b = w*4..w*4+3
    const int lane = t & 31, w = t >> 5;
    #pragma unroll
    for (int j = 0; j < 4; j++) {
        const int b = w * 4 + j;
        float m = fmaxf(fmaxf(es[b * CH + lane], es[b * CH + lane + 32]),
                        fmaxf(es[b * CH + lane + 64], es[b * CH + lane + 96]));
        #pragma unroll
        for (int o = 16; o > 0; o >>= 1) m = fmaxf(m, __shfl_xor_sync(0xffffffffu, m, o));
        if (lane == 0) { cm[b] = m; g_cmax[b * NCH + blockIdx.x] = m; }
    }
    __syncthreads();

    // exp in place: 4096 elements, 16 per thread
    #pragma unroll
    for (int i = t; i < B * CH; i += NT)
        es[i] = __expf(es[i] - cm[i >> 7]);
    __syncthreads();

    // chunk sum per b
    #pragma unroll
    for (int j = 0; j < 4; j++) {
        const int b = w * 4 + j;
        float s = es[b * CH + lane] + es[b * CH + lane + 32]
                + es[b * CH + lane + 64] + es[b * CH + lane + 96];
        #pragma unroll
        for (int o = 16; o > 0; o >>= 1) s += __shfl_xor_sync(0xffffffffu, s, o);
        if (lane == 0) g_csum[b * NCH + blockIdx.x] = s;
    }

    // ---- Phase B: acc[2][8]; d0 = tt, d1 = tt+64 ----
    float acc0[8], acc1[8];
    #pragma unroll
    for (int j = 0; j < 8; j++) { acc0[j] = 0.f; acc1[j] = 0.f; }

    #pragma unroll 2
    for (int n4 = 0; n4 < CH / 4; n4++) {
        const int n = n4 * 4;
        float p0 = ys[(n + 0) * YSTRIDE + tt];
        float p1 = ys[(n + 1) * YSTRIDE + tt];
        float p2 = ys[(n + 2) * YSTRIDE + tt];
        float p3 = ys[(n + 3) * YSTRIDE + tt];
        float q0 = ys[(n + 0) * YSTRIDE + tt + 64];
        float q1 = ys[(n + 1) * YSTRIDE + tt + 64];
        float q2 = ys[(n + 2) * YSTRIDE + tt + 64];
        float q3 = ys[(n + 3) * YSTRIDE + tt + 64];
        #pragma unroll
        for (int j = 0; j < 8; j++) {
            float4 e = *reinterpret_cast<const float4*>(&es[(bbase + j) * CH + n]); // broadcast
            acc0[j] = fmaf(e.x, p0, acc0[j]);
            acc0[j] = fmaf(e.y, p1, acc0[j]);
            acc0[j] = fmaf(e.z, p2, acc0[j]);
            acc0[j] = fmaf(e.w, p3, acc0[j]);
            acc1[j] = fmaf(e.x, q0, acc1[j]);
            acc1[j] = fmaf(e.y, q1, acc1[j]);
            acc1[j] = fmaf(e.z, q2, acc1[j]);
            acc1[j] = fmaf(e.w, q3, acc1[j]);
        }
    }

    // coalesced stores: [c][b][d]
    float* pv = g_cvec + (size_t)blockIdx.x * B * D;
    #pragma unroll
    for (int j = 0; j < 8; j++) {
        pv[(bbase + j) * D + tt]      = acc0[j];
        pv[(bbase + j) * D + tt + 64] = acc1[j];
    }
}

// block-parallel global max over one b row of g_cmax (128 threads)
__device__ __forceinline__ float block_max_cmax(int b, int t, int lane, int w,
                                                float* red, float& c0, float& c1) {
    __shared__ float sMx;
    c0 = g_cmax[b * NCH + t];
    c1 = g_cmax[b * NCH + t + 128];
    float m = fmaxf(c0, c1);
    #pragma unroll
    for (int o = 16; o > 0; o >>= 1) m = fmaxf(m, __shfl_xor_sync(0xffffffffu, m, o));
    if (lane == 0) red[w] = m;
    __syncthreads();
    if (t == 0) sMx = fmaxf(fmaxf(red[0], red[1]), fmaxf(red[2], red[3]));
    __syncthreads();
    return sMx;
}

// ---------------------------------------------------------------------------
// K2: stage-1 reduce. Grid = B*NCG = 256 CTAs, 128 threads (t = d).
// ---------------------------------------------------------------------------
__global__ __launch_bounds__(128) void k_part() {
    __shared__ float sc[NCH];
    __shared__ float red[4];
    const int t = threadIdx.x, lane = t & 31, w = t >> 5;
    const int b = blockIdx.x >> 3;
    const int cg = blockIdx.x & (NCG - 1);

    float c0, c1;
    const float M = block_max_cmax(b, t, lane, w, red, c0, c1);
    sc[t] = __expf(c0 - M);
    sc[t + 128] = __expf(c1 - M);
    __syncthreads();

    float v = 0.f;
    #pragma unroll
    for (int j = 0; j < CPG; j++) {
        const int c = cg * CPG + j;
        v = fmaf(sc[c], g_cvec[((size_t)c * B + b) * D + t], v);  // 512B coalesced
    }
    g_pvec2[(b * NCG + cg) * D + t] = v;
}

// ---------------------------------------------------------------------------
// K3: stage-2. Grid = B, 128 threads (t = d). Recompute M, SE; epilogue.
// ---------------------------------------------------------------------------
__global__ __launch_bounds__(128) void k_fin2(const float* __restrict__ x,
                                              const float* __restrict__ al,
                                              float* __restrict__ out) {
    __shared__ float red[4];
    __shared__ float sSE;
    const int t = threadIdx.x, lane = t & 31, w = t >> 5;
    const int b = blockIdx.x;

    float c0, c1;
    const float M = block_max_cmax(b, t, lane, w, red, c0, c1);

    float ps = fmaf(__expf(c0 - M), g_csum[b * NCH + t],
                    __expf(c1 - M) * g_csum[b * NCH + t + 128]);
    #pragma unroll
    for (int o = 16; o > 0; o >>= 1) ps += __shfl_xor_sync(0xffffffffu, ps, o);
    if (lane == 0) red[w] = ps;
    __syncthreads();
    if (t == 0) sSE = red[0] + red[1] + red[2] + red[3];
    __syncthreads();

    float v = 0.f;
    #pragma unroll
    for (int cg = 0; cg < NCG; cg++)
        v += g_pvec2[(b * NCG + cg) * D + t];   // MLP=8, coalesced

    float a = al[b];
    float var = 1.f - a;
    out[b * D + t] = (x[b * D + t] - sqrtf(a) * (v / sSE)) * rsqrtf(var);
}

extern "C" void kernel_launch(void* const* d_in, const int* in_sizes, int n_in,
                              void* d_out, int out_size) {
    const float* x  = (const float*)d_in[0];   // inputs [B, D]
    const float* al = (const float*)d_in[1];   // alphas [B]
    const float* y  = (const float*)d_in[2];   // data_batch [N, D]
    float* out = (float*)d_out;                // [B, D]

    const size_t SMEM = (CH * YSTRIDE + B * D + B * CH) * sizeof(float);  // ~98 KB
    cudaFuncSetAttribute(k_chunk, cudaFuncAttributeMaxDynamicSharedMemorySize, (int)SMEM);

    k_chunk<<<NCH, NT, SMEM>>>(x, al, y);
    k_part<<<B * NCG, 128>>>();
    k_fin2<<<B, 128>>>(x, al, out);
}

// round 11
// speedup vs baseline: 1.1390x; 1.1390x over previous
#include <cuda_runtime.h>
#include <cuda_fp16.h>
#include <math.h>
#include <stdint.h>

#define B 32
#define N 32768
#define D 128
#define CH 128
#define NCH (N / CH)       // 256
#define NT 256
#define NCG 8
#define CPG (NCH / NCG)

#define PITCH 136          // halves per fp16 tile row (272 B, 16B-aligned, conflict-free)
#define PITCHF 132         // floats per staging row (528 B)

// smem byte offsets
#define SM_YH 0            // [128][PITCH] fp16  34816 B
#define SM_YL 34816        // [128][PITCH] fp16
#define SM_XT 69632        // [64][PITCH] fp16   17408 B
#define SM_ES 87040        // [64][PITCH] fp16   17408 B
#define SM_Y2 104448       // float[128]
#define SM_SA 104960       // float[32]
#define SM_SC 105088       // float[32]
#define SM_RED 105216      // float[8][32]
#define SM_CM 106240       // float[32]
#define SMEM_TOTAL 106496
#define SM_PS 0            // f32 [64][PITCHF] staging, aliases Y tiles after GEMM2

#define L2E 1.44269504f

// gmem scratch (no allocations allowed)
__device__ float g_cmax[B * NCH];
__device__ float g_csum[B * NCH];
__device__ float g_cvec[NCH * B * D];      // [c][b][d]
__device__ float g_pvec2[B * NCG * D];
__device__ float g_sA[B], g_sC[B];
__device__ __align__(16) unsigned char g_xtile[64 * PITCH * 2];   // [xh(32)|xl(32)][128k] padded

__device__ __forceinline__ uint32_t s2u(const void* p) {
    uint32_t a;
    asm("{ .reg .u64 t; cvta.to.shared.u64 t, %1; cvt.u32.u64 %0, t; }" : "=r"(a) : "l"(p));
    return a;
}
__device__ __forceinline__ float ex2f(float x) {
    float y; asm("ex2.approx.f32 %0, %1;" : "=f"(y) : "f"(x)); return y;
}
__device__ __forceinline__ void ldsm4(uint32_t a, uint32_t r[4]) {
    asm volatile("ldmatrix.sync.aligned.m8n8.x4.shared.b16 {%0,%1,%2,%3}, [%4];"
        : "=r"(r[0]), "=r"(r[1]), "=r"(r[2]), "=r"(r[3]) : "r"(a));
}
__device__ __forceinline__ void ldsm2(uint32_t a, uint32_t r[2]) {
    asm volatile("ldmatrix.sync.aligned.m8n8.x2.shared.b16 {%0,%1}, [%2];"
        : "=r"(r[0]), "=r"(r[1]) : "r"(a));
}
__device__ __forceinline__ void ldsm2t(uint32_t a, uint32_t r[2]) {
    asm volatile("ldmatrix.sync.aligned.m8n8.x2.trans.shared.b16 {%0,%1}, [%2];"
        : "=r"(r[0]), "=r"(r[1]) : "r"(a));
}
__device__ __forceinline__ void mma16816(float c[4], const uint32_t a[4], const uint32_t b[2]) {
    asm volatile("mma.sync.aligned.m16n8k16.row.col.f32.f16.f16.f32 "
        "{%0,%1,%2,%3}, {%4,%5,%6,%7}, {%8,%9}, {%0,%1,%2,%3};"
        : "+f"(c[0]), "+f"(c[1]), "+f"(c[2]), "+f"(c[3])
        : "r"(a[0]), "r"(a[1]), "r"(a[2]), "r"(a[3]), "r"(b[0]), "r"(b[1]));
}

// ---------------------------------------------------------------------------
// K0: prep — sA/sC consts; x~ tile [64 rows: xh(b) | xl(b)] x 128 k, fp16.
// ---------------------------------------------------------------------------
__global__ __launch_bounds__(256) void k_prep(const float* __restrict__ x,
                                              const float* __restrict__ al) {
    __shared__ float ssc[B];
    const int t = threadIdx.x;
    if (t < B) {
        float a = al[t], var = 1.0f - a;
        float x2 = 0.f;
        #pragma unroll 8
        for (int d = 0; d < D; d++) { float v = x[t * D + d]; x2 = fmaf(v, v, x2); }
        g_sA[t] = -(0.5f * (float)D * logf(var) + 0.5f / var * x2);
        g_sC[t] = 0.5f * a / var;
        ssc[t] = sqrtf(a) / var;
    }
    __syncthreads();
    const int b = t >> 3, kb = (t & 7) * 16;
    const float sc = ssc[b];
    #pragma unroll
    for (int j = 0; j < 16; j++) {
        const int k = kb + j;
        float xv = sc * x[b * D + k];
        __half h = __float2half_rn(xv);
        __half lo = __float2half_rn(xv - __half2float(h));
        *(__half*)(g_xtile + ((size_t)b * PITCH + k) * 2) = h;
        *(__half*)(g_xtile + ((size_t)(b + 32) * PITCH + k) * 2) = lo;
    }
}

// ---------------------------------------------------------------------------
// K1: HMMA chunk kernel. Grid NCH, 256 threads = 8 warps.
// ---------------------------------------------------------------------------
__global__ __launch_bounds__(NT) void k_chunk(const float* __restrict__ y) {
    extern __shared__ char smem[];
    const uint32_t sb = s2u(smem);
    const int t = threadIdx.x, w = t >> 5, lane = t & 31;
    const int c = blockIdx.x;

    // copy x~ tile, consts
    {
        const float4* src = (const float4*)g_xtile;
        float4* dst = (float4*)(smem + SM_XT);
        #pragma unroll
        for (int i = t; i < 64 * PITCH * 2 / 16; i += NT) dst[i] = src[i];
    }
    if (t < B) {
        *(float*)(smem + SM_SA + t * 4) = g_sA[t];
        *(float*)(smem + SM_SC + t * 4) = g_sC[t];
    }

    // stage y: fp32 -> yh/yl fp16 tiles + y2 per row
    {
        const float4* y4 = (const float4*)(y + (size_t)c * CH * D);
        #pragma unroll
        for (int kk = 0; kk < 16; kk++) {
            const int i = kk * NT + t;
            const int row = i >> 5;            // whole warp same row
            const int c4 = (i & 31) * 4;
            float4 v = y4[i];
            float sq = fmaf(v.x, v.x, fmaf(v.y, v.y, fmaf(v.z, v.z, v.w * v.w)));
            #pragma unroll
            for (int o = 16; o > 0; o >>= 1) sq += __shfl_xor_sync(0xffffffffu, sq, o);
            if (lane == 0) *(float*)(smem + SM_Y2 + row * 4) = sq;
            __half hx = __float2half_rn(v.x), hy = __float2half_rn(v.y);
            __half hz = __float2half_rn(v.z), hw = __float2half_rn(v.w);
            __half2 h01 = __halves2half2(hx, hy), h23 = __halves2half2(hz, hw);
            __half2 l01 = __halves2half2(__float2half_rn(v.x - __half2float(hx)),
                                         __float2half_rn(v.y - __half2float(hy)));
            __half2 l23 = __halves2half2(__float2half_rn(v.z - __half2float(hz)),
                                         __float2half_rn(v.w - __half2float(hw)));
            const uint32_t off = (uint32_t)(row * PITCH + c4) * 2;
            *(__half2*)(smem + SM_YH + off) = h01;
            *(__half2*)(smem + SM_YH + off + 4) = h23;
            *(__half2*)(smem + SM_YL + off) = l01;
            *(__half2*)(smem + SM_YL + off + 4) = l23;
        }
    }
    __syncthreads();

    // ---- GEMM1: L[n=128, bp=64] = (Yh + Yl) * XT^T. warp owns 16 n-rows ----
    float acc[8][4];
    #pragma unroll
    for (int j = 0; j < 8; j++)
        #pragma unroll
        for (int q = 0; q < 4; q++) acc[j][q] = 0.f;

    const int nb = w * 16;
    const uint32_t aAddr = sb + SM_YH + (uint32_t)(nb + (lane & 15)) * (PITCH * 2)
                         + (uint32_t)(((lane >> 4) << 3) * 2);
    const uint32_t bAddr = sb + SM_XT + (uint32_t)(lane & 7) * (PITCH * 2)
                         + (uint32_t)((((lane >> 3) & 1) << 3) * 2);
    #pragma unroll
    for (int ks = 0; ks < 8; ks++) {
        const uint32_t kOff = (uint32_t)(ks * 32);      // 16 halves
        uint32_t ah[4], alr[4];
        ldsm4(aAddr + kOff, ah);
        ldsm4(aAddr + (SM_YL - SM_YH) + kOff, alr);
        #pragma unroll
        for (int j = 0; j < 8; j++) {
            uint32_t bb[2];
            ldsm2(bAddr + (uint32_t)(j * 8) * (PITCH * 2) + kOff, bb);
            mma16816(acc[j], ah, bb);
            mma16816(acc[j], alr, bb);
        }
    }

    // ---- epilogue 1 ----
    const int n0 = nb + (lane >> 2);
    const float y20 = *(const float*)(smem + SM_Y2 + n0 * 4);
    const float y21 = *(const float*)(smem + SM_Y2 + (n0 + 8) * 4);
    const float* sAs = (const float*)(smem + SM_SA);
    const float* sCs = (const float*)(smem + SM_SC);
    float* red = (float*)(smem + SM_RED);
    float* cmv = (float*)(smem + SM_CM);

    float lv[4][4];
    float mx[4][2];
    #pragma unroll
    for (int j = 0; j < 4; j++) {
        #pragma unroll
        for (int cc = 0; cc < 2; cc++) {
            const int b2 = j * 8 + 2 * (lane & 3) + cc;
            lv[j][cc]     = acc[j][cc]     + acc[j + 4][cc]     + sAs[b2] - sCs[b2] * y20;
            lv[j][cc + 2] = acc[j][cc + 2] + acc[j + 4][cc + 2] + sAs[b2] - sCs[b2] * y21;
            float m = fmaxf(lv[j][cc], lv[j][cc + 2]);
            #pragma unroll
            for (int o = 4; o < 32; o <<= 1) m = fmaxf(m, __shfl_xor_sync(0xffffffffu, m, o));
            mx[j][cc] = m;
        }
    }
    if (lane < 4) {
        #pragma unroll
        for (int j = 0; j < 4; j++)
            #pragma unroll
            for (int cc = 0; cc < 2; cc++)
                red[w * 32 + j * 8 + 2 * lane + cc] = mx[j][cc];
    }
    __syncthreads();
    if (t < 32) {
        float m = -3.4e38f;
        #pragma unroll
        for (int w2 = 0; w2 < 8; w2++) m = fmaxf(m, red[w2 * 32 + t]);
        cmv[t] = m;
        g_cmax[t * NCH + c] = m;
    }
    __syncthreads();

    float sv[4][2];
    #pragma unroll
    for (int j = 0; j < 4; j++) {
        #pragma unroll
        for (int cc = 0; cc < 2; cc++) {
            const int b2 = j * 8 + 2 * (lane & 3) + cc;
            const float cmb = cmv[b2];
            float e0 = ex2f((lv[j][cc] - cmb) * L2E);
            float e1 = ex2f((lv[j][cc + 2] - cmb) * L2E);
            __half h0 = __float2half_rn(e0), h1 = __float2half_rn(e1);
            __half l0 = __float2half_rn(e0 - __half2float(h0));
            __half l1 = __float2half_rn(e1 - __half2float(h1));
            *(__half*)(smem + SM_ES + ((uint32_t)b2 * PITCH + n0) * 2) = h0;
            *(__half*)(smem + SM_ES + ((uint32_t)b2 * PITCH + n0 + 8) * 2) = h1;
            *(__half*)(smem + SM_ES + ((uint32_t)(b2 + 32) * PITCH + n0) * 2) = l0;
            *(__half*)(smem + SM_ES + ((uint32_t)(b2 + 32) * PITCH + n0 + 8) * 2) = l1;
            float s = e0 + e1;
            #pragma unroll
            for (int o = 4; o < 32; o <<= 1) s += __shfl_xor_sync(0xffffffffu, s, o);
            sv[j][cc] = s;
        }
    }
    if (lane < 4) {
        #pragma unroll
        for (int j = 0; j < 4; j++)
            #pragma unroll
            for (int cc = 0; cc < 2; cc++)
                red[w * 32 + j * 8 + 2 * lane + cc] = sv[j][cc];
    }
    __syncthreads();      // ES + sums visible
    if (t < 32) {
        float s = 0.f;
        #pragma unroll
        for (int w2 = 0; w2 < 8; w2++) s += red[w2 * 32 + t];
        g_csum[t * NCH + c] = s;
    }

    // ---- GEMM2: V[bp=64, d=128] = ES * (Yh + Yl). warp: 16 bp-rows x 64 d ----
    float a2[8][4];
    #pragma unroll
    for (int j = 0; j < 8; j++)
        #pragma unroll
        for (int q = 0; q < 4; q++) a2[j][q] = 0.f;

    const int mb = (w & 3) * 16;
    const int db = (w >> 2) * 64;
    const uint32_t aeAddr = sb + SM_ES + (uint32_t)(mb + (lane & 15)) * (PITCH * 2)
                          + (uint32_t)(((lane >> 4) << 3) * 2);
    const uint32_t btRow = (uint32_t)(lane & 15) * (PITCH * 2);
    #pragma unroll
    for (int ks = 0; ks < 8; ks++) {
        const uint32_t nOff = (uint32_t)(ks * 16);
        uint32_t ae[4];
        ldsm4(aeAddr + nOff * 2, ae);
        const uint32_t ybase = nOff * (PITCH * 2) + btRow;
        #pragma unroll
        for (int j = 0; j < 8; j++) {
            const uint32_t dOff = (uint32_t)(db + j * 8) * 2;
            uint32_t bh[2], bl[2];
            ldsm2t(sb + SM_YH + ybase + dOff, bh);
            ldsm2t(sb + SM_YL + ybase + dOff, bl);
            mma16816(a2[j], ae, bh);
            mma16816(a2[j], ae, bl);
        }
    }
    __syncthreads();      // Y tiles dead; reuse as PS staging

    // stage fragments to PS[64][PITCHF] f32
    const int r0 = mb + (lane >> 2);
    #pragma unroll
    for (int j = 0; j < 8; j++) {
        const int dc = db + j * 8 + 2 * (lane & 3);
        *(float2*)(smem + SM_PS + ((uint32_t)r0 * PITCHF + dc) * 4) =
            make_float2(a2[j][0], a2[j][1]);
        *(float2*)(smem + SM_PS + ((uint32_t)(r0 + 8) * PITCHF + dc) * 4) =
            make_float2(a2[j][2], a2[j][3]);
    }
    __syncthreads();

    // combine ph + pl rows, coalesced store g_cvec[c][b][d]
    #pragma unroll
    for (int i4 = t; i4 < 1024; i4 += NT) {
        const int b2 = i4 >> 5, d4 = (i4 & 31) * 4;
        float4 pa = *(const float4*)(smem + SM_PS + ((uint32_t)b2 * PITCHF + d4) * 4);
        float4 pb = *(const float4*)(smem + SM_PS + ((uint32_t)(b2 + 32) * PITCHF + d4) * 4);
        float4 o = make_float4(pa.x + pb.x, pa.y + pb.y, pa.z + pb.z, pa.w + pb.w);
        *(float4*)(g_cvec + ((size_t)c * B + b2) * D + d4) = o;
    }
}

// ---------------------------------------------------------------------------
// K2/K3: reduction kernels (proven from R9)
// ---------------------------------------------------------------------------
__device__ __forceinline__ float block_max_cmax(int b, int t, int lane, int w,
                                                float* red, float& c0, float& c1) {
    __shared__ float sMx;
    c0 = g_cmax[b * NCH + t];
    c1 = g_cmax[b * NCH + t + 128];
    float m = fmaxf(c0, c1);
    #pragma unroll
    for (int o = 16; o > 0; o >>= 1) m = fmaxf(m, __shfl_xor_sync(0xffffffffu, m, o));
    if (lane == 0) red[w] = m;
    __syncthreads();
    if (t == 0) sMx = fmaxf(fmaxf(red[0], red[1]), fmaxf(red[2], red[3]));
    __syncthreads();
    return sMx;
}

__global__ __launch_bounds__(128) void k_part() {
    __shared__ float sc[NCH];
    __shared__ float red[4];
    const int t = threadIdx.x, lane = t & 31, w = t >> 5;
    const int b = blockIdx.x >> 3;
    const int cg = blockIdx.x & (NCG - 1);
    float c0, c1;
    const float M = block_max_cmax(b, t, lane, w, red, c0, c1);
    sc[t] = __expf(c0 - M);
    sc[t + 128] = __expf(c1 - M);
    __syncthreads();
    float v = 0.f;
    #pragma unroll
    for (int j = 0; j < CPG; j++) {
        const int cc = cg * CPG + j;
        v = fmaf(sc[cc], g_cvec[((size_t)cc * B + b) * D + t], v);
    }
    g_pvec2[(b * NCG + cg) * D + t] = v;
}

__global__ __launch_bounds__(128) void k_fin2(const float* __restrict__ x,
                                              const float* __restrict__ al,
                                              float* __restrict__ out) {
    __shared__ float red[4];
    __shared__ float sSE;
    const int t = threadIdx.x, lane = t & 31, w = t >> 5;
    const int b = blockIdx.x;
    float c0, c1;
    const float M = block_max_cmax(b, t, lane, w, red, c0, c1);
    float ps = fmaf(__expf(c0 - M), g_csum[b * NCH + t],
                    __expf(c1 - M) * g_csum[b * NCH + t + 128]);
    #pragma unroll
    for (int o = 16; o > 0; o >>= 1) ps += __shfl_xor_sync(0xffffffffu, ps, o);
    if (lane == 0) red[w] = ps;
    __syncthreads();
    if (t == 0) sSE = red[0] + red[1] + red[2] + red[3];
    __syncthreads();
    float v = 0.f;
    #pragma unroll
    for (int cg = 0; cg < NCG; cg++)
        v += g_pvec2[(b * NCG + cg) * D + t];
    float a = al[b];
    float var = 1.f - a;
    out[b * D + t] = (x[b * D + t] - sqrtf(a) * (v / sSE)) * rsqrtf(var);
}

extern "C" void kernel_launch(void* const* d_in, const int* in_sizes, int n_in,
                              void* d_out, int out_size) {
    const float* x  = (const float*)d_in[0];
    const float* al = (const float*)d_in[1];
    const float* y  = (const float*)d_in[2];
    float* out = (float*)d_out;

    cudaFuncSetAttribute(k_chunk, cudaFuncAttributeMaxDynamicSharedMemorySize, SMEM_TOTAL);

    k_prep<<<1, 256>>>(x, al);
    k_chunk<<<NCH, NT, SMEM_TOTAL>>>(y);
    k_part<<<B * NCG, 128>>>();
    k_fin2<<<B, 128>>>(x, al, out);
}

// round 12
// speedup vs baseline: 1.4706x; 1.2911x over previous
#include <cuda_runtime.h>
#include <cuda_fp16.h>
#include <math.h>
#include <stdint.h>

#define B 32
#define N 32768
#define D 128
#define CH 128
#define NCH (N / CH)       // 256

#define NT 256
#define PITCH 136          // halves per fp16 tile row (272 B, 16B-aligned)
#define PITCHF 132         // floats per staging row

// smem byte offsets (k_chunk)
#define SM_YH 0            // [128][PITCH] fp16  34816 B
#define SM_YL 34816
#define SM_XT 69632        // [64][PITCH] fp16   17408 B
#define SM_ES 87040        // [64][PITCH] fp16
#define SM_Y2 104448       // float[128]
#define SM_SA 104960       // float[32]
#define SM_SC 105088
#define SM_RED 105216      // float[8][32]
#define SM_CM 106240       // float[32]
#define SM_SSC 106368      // float[32]
#define SM_X2 106496       // float[32]
#define SM_VAR 106624      // float[32]
#define SMEM_TOTAL 106752
#define SM_PS 0            // f32 [64][PITCHF] staging, aliases Y tiles after GEMM2

#define L2E 1.44269504f

// gmem scratch (no allocations allowed)
__device__ float g_cmax[B * NCH];
__device__ float g_csum[B * NCH];
__device__ float g_cvec[NCH * B * D];      // [c][b][d]

__device__ __forceinline__ uint32_t s2u(const void* p) {
    uint32_t a;
    asm("{ .reg .u64 t; cvta.to.shared.u64 t, %1; cvt.u32.u64 %0, t; }" : "=r"(a) : "l"(p));
    return a;
}
__device__ __forceinline__ float ex2f(float x) {
    float y; asm("ex2.approx.f32 %0, %1;" : "=f"(y) : "f"(x)); return y;
}
__device__ __forceinline__ void ldsm4(uint32_t a, uint32_t r[4]) {
    asm volatile("ldmatrix.sync.aligned.m8n8.x4.shared.b16 {%0,%1,%2,%3}, [%4];"
        : "=r"(r[0]), "=r"(r[1]), "=r"(r[2]), "=r"(r[3]) : "r"(a));
}
__device__ __forceinline__ void ldsm2(uint32_t a, uint32_t r[2]) {
    asm volatile("ldmatrix.sync.aligned.m8n8.x2.shared.b16 {%0,%1}, [%2];"
        : "=r"(r[0]), "=r"(r[1]) : "r"(a));
}
__device__ __forceinline__ void ldsm2t(uint32_t a, uint32_t r[2]) {
    asm volatile("ldmatrix.sync.aligned.m8n8.x2.trans.shared.b16 {%0,%1}, [%2];"
        : "=r"(r[0]), "=r"(r[1]) : "r"(a));
}
__device__ __forceinline__ void mma16816(float c[4], const uint32_t a[4], const uint32_t b[2]) {
    asm volatile("mma.sync.aligned.m16n8k16.row.col.f32.f16.f16.f32 "
        "{%0,%1,%2,%3}, {%4,%5,%6,%7}, {%8,%9}, {%0,%1,%2,%3};"
        : "+f"(c[0]), "+f"(c[1]), "+f"(c[2]), "+f"(c[3])
        : "r"(a[0]), "r"(a[1]), "r"(a[2]), "r"(a[3]), "r"(b[0]), "r"(b[1]));
}

// ---------------------------------------------------------------------------
// K1: HMMA chunk kernel with in-CTA prep. Grid NCH, 256 threads = 8 warps.
// ---------------------------------------------------------------------------
__global__ __launch_bounds__(NT) void k_chunk(const float* __restrict__ x,
                                              const float* __restrict__ al,
                                              const float* __restrict__ y) {
    extern __shared__ char smem[];
    const uint32_t sb = s2u(smem);
    const int t = threadIdx.x, w = t >> 5, lane = t & 31;
    const int c = blockIdx.x;

    // alpha-derived consts (no x2 dependency)
    if (t < B) {
        float a = al[t], var = 1.0f - a;
        *(float*)(smem + SM_VAR + t * 4) = var;
        *(float*)(smem + SM_SSC + t * 4) = sqrtf(a) / var;
        *(float*)(smem + SM_SC + t * 4) = 0.5f * a / var;
    }
    __syncthreads();

    // build x~ tile in smem + x2 partials (8 threads per b, 16 k each)
    {
        const int b = t >> 3, kb = (t & 7) * 16;
        const float sc_ = *(const float*)(smem + SM_SSC + b * 4);
        float x2p = 0.f;
        #pragma unroll
        for (int j = 0; j < 16; j++) {
            const int k = kb + j;
            float raw = x[b * D + k];
            x2p = fmaf(raw, raw, x2p);
            float xv = sc_ * raw;
            __half h = __float2half_rn(xv);
            __half lo = __float2half_rn(xv - __half2float(h));
            *(__half*)(smem + SM_XT + ((uint32_t)b * PITCH + k) * 2) = h;
            *(__half*)(smem + SM_XT + ((uint32_t)(b + 32) * PITCH + k) * 2) = lo;
        }
        x2p += __shfl_xor_sync(0xffffffffu, x2p, 1);
        x2p += __shfl_xor_sync(0xffffffffu, x2p, 2);
        x2p += __shfl_xor_sync(0xffffffffu, x2p, 4);
        if ((t & 7) == 0) *(float*)(smem + SM_X2 + b * 4) = x2p;
    }

    // stage y: fp32 -> yh/yl fp16 tiles + y2 per row
    {
        const float4* y4 = (const float4*)(y + (size_t)c * CH * D);
        #pragma unroll
        for (int kk = 0; kk < 16; kk++) {
            const int i = kk * NT + t;
            const int row = i >> 5;            // whole warp same row
            const int c4 = (i & 31) * 4;
            float4 v = y4[i];
            float sq = fmaf(v.x, v.x, fmaf(v.y, v.y, fmaf(v.z, v.z, v.w * v.w)));
            #pragma unroll
            for (int o = 16; o > 0; o >>= 1) sq += __shfl_xor_sync(0xffffffffu, sq, o);
            if (lane == 0) *(float*)(smem + SM_Y2 + row * 4) = sq;
            __half hx = __float2half_rn(v.x), hy = __float2half_rn(v.y);
            __half hz = __float2half_rn(v.z), hw = __float2half_rn(v.w);
            __half2 h01 = __halves2half2(hx, hy), h23 = __halves2half2(hz, hw);
            __half2 l01 = __halves2half2(__float2half_rn(v.x - __half2float(hx)),
                                         __float2half_rn(v.y - __half2float(hy)));
            __half2 l23 = __halves2half2(__float2half_rn(v.z - __half2float(hz)),
                                         __float2half_rn(v.w - __half2float(hw)));
            const uint32_t off = (uint32_t)(row * PITCH + c4) * 2;
            *(__half2*)(smem + SM_YH + off) = h01;
            *(__half2*)(smem + SM_YH + off + 4) = h23;
            *(__half2*)(smem + SM_YL + off) = l01;
            *(__half2*)(smem + SM_YL + off + 4) = l23;
        }
    }
    __syncthreads();

    // finish sA (needs x2 from all 256 threads)
    if (t < B) {
        float var = *(const float*)(smem + SM_VAR + t * 4);
        float x2 = *(const float*)(smem + SM_X2 + t * 4);
        *(float*)(smem + SM_SA + t * 4) = -(0.5f * (float)D * logf(var) + 0.5f / var * x2);
    }
    __syncthreads();

    // ---- GEMM1: L[n=128, bp=64] = (Yh + Yl) * XT^T. warp owns 16 n-rows ----
    float acc[8][4];
    #pragma unroll
    for (int j = 0; j < 8; j++)
        #pragma unroll
        for (int q = 0; q < 4; q++) acc[j][q] = 0.f;

    const int nb = w * 16;
    const uint32_t aAddr = sb + SM_YH + (uint32_t)(nb + (lane & 15)) * (PITCH * 2)
                         + (uint32_t)(((lane >> 4) << 3) * 2);
    const uint32_t bAddr = sb + SM_XT + (uint32_t)(lane & 7) * (PITCH * 2)
                         + (uint32_t)((((lane >> 3) & 1) << 3) * 2);
    #pragma unroll
    for (int ks = 0; ks < 8; ks++) {
        const uint32_t kOff = (uint32_t)(ks * 32);      // 16 halves
        uint32_t ah[4], alr[4];
        ldsm4(aAddr + kOff, ah);
        ldsm4(aAddr + (SM_YL - SM_YH) + kOff, alr);
        #pragma unroll
        for (int j = 0; j < 8; j++) {
            uint32_t bb[2];
            ldsm2(bAddr + (uint32_t)(j * 8) * (PITCH * 2) + kOff, bb);
            mma16816(acc[j], ah, bb);
            mma16816(acc[j], alr, bb);
        }
    }

    // ---- epilogue 1 ----
    const int n0 = nb + (lane >> 2);
    const float y20 = *(const float*)(smem + SM_Y2 + n0 * 4);
    const float y21 = *(const float*)(smem + SM_Y2 + (n0 + 8) * 4);
    const float* sAs = (const float*)(smem + SM_SA);
    const float* sCs = (const float*)(smem + SM_SC);
    float* red = (float*)(smem + SM_RED);
    float* cmv = (float*)(smem + SM_CM);

    float lv[4][4];
    float mx[4][2];
    #pragma unroll
    for (int j = 0; j < 4; j++) {
        #pragma unroll
        for (int cc = 0; cc < 2; cc++) {
            const int b2 = j * 8 + 2 * (lane & 3) + cc;
            lv[j][cc]     = acc[j][cc]     + acc[j + 4][cc]     + sAs[b2] - sCs[b2] * y20;
            lv[j][cc + 2] = acc[j][cc + 2] + acc[j + 4][cc + 2] + sAs[b2] - sCs[b2] * y21;
            float m = fmaxf(lv[j][cc], lv[j][cc + 2]);
            #pragma unroll
            for (int o = 4; o < 32; o <<= 1) m = fmaxf(m, __shfl_xor_sync(0xffffffffu, m, o));
            mx[j][cc] = m;
        }
    }
    if (lane < 4) {
        #pragma unroll
        for (int j = 0; j < 4; j++)
            #pragma unroll
            for (int cc = 0; cc < 2; cc++)
                red[w * 32 + j * 8 + 2 * lane + cc] = mx[j][cc];
    }
    __syncthreads();
    if (t < 32) {
        float m = -3.4e38f;
        #pragma unroll
        for (int w2 = 0; w2 < 8; w2++) m = fmaxf(m, red[w2 * 32 + t]);
        cmv[t] = m;
        g_cmax[t * NCH + c] = m;
    }
    __syncthreads();

    float sv[4][2];
    #pragma unroll
    for (int j = 0; j < 4; j++) {
        #pragma unroll
        for (int cc = 0; cc < 2; cc++) {
            const int b2 = j * 8 + 2 * (lane & 3) + cc;
            const float cmb = cmv[b2];
            float e0 = ex2f((lv[j][cc] - cmb) * L2E);
            float e1 = ex2f((lv[j][cc + 2] - cmb) * L2E);
            __half h0 = __float2half_rn(e0), h1 = __float2half_rn(e1);
            __half l0 = __float2half_rn(e0 - __half2float(h0));
            __half l1 = __float2half_rn(e1 - __half2float(h1));
            *(__half*)(smem + SM_ES + ((uint32_t)b2 * PITCH + n0) * 2) = h0;
            *(__half*)(smem + SM_ES + ((uint32_t)b2 * PITCH + n0 + 8) * 2) = h1;
            *(__half*)(smem + SM_ES + ((uint32_t)(b2 + 32) * PITCH + n0) * 2) = l0;
            *(__half*)(smem + SM_ES + ((uint32_t)(b2 + 32) * PITCH + n0 + 8) * 2) = l1;
            float s = e0 + e1;
            #pragma unroll
            for (int o = 4; o < 32; o <<= 1) s += __shfl_xor_sync(0xffffffffu, s, o);
            sv[j][cc] = s;
        }
    }
    if (lane < 4) {
        #pragma unroll
        for (int j = 0; j < 4; j++)
            #pragma unroll
            for (int cc = 0; cc < 2; cc++)
                red[w * 32 + j * 8 + 2 * lane + cc] = sv[j][cc];
    }
    __syncthreads();      // ES + sums visible
    if (t < 32) {
        float s = 0.f;
        #pragma unroll
        for (int w2 = 0; w2 < 8; w2++) s += red[w2 * 32 + t];
        g_csum[t * NCH + c] = s;
    }

    // ---- GEMM2: V[bp=64, d=128] = ES * (Yh + Yl). warp: 16 bp-rows x 64 d ----
    float a2[8][4];
    #pragma unroll
    for (int j = 0; j < 8; j++)
        #pragma unroll
        for (int q = 0; q < 4; q++) a2[j][q] = 0.f;

    const int mb = (w & 3) * 16;
    const int db = (w >> 2) * 64;
    const uint32_t aeAddr = sb + SM_ES + (uint32_t)(mb + (lane & 15)) * (PITCH * 2)
                          + (uint32_t)(((lane >> 4) << 3) * 2);
    const uint32_t btRow = (uint32_t)(lane & 15) * (PITCH * 2);
    #pragma unroll
    for (int ks = 0; ks < 8; ks++) {
        const uint32_t nOff = (uint32_t)(ks * 16);
        uint32_t ae[4];
        ldsm4(aeAddr + nOff * 2, ae);
        const uint32_t ybase = nOff * (PITCH * 2) + btRow;
        #pragma unroll
        for (int j = 0; j < 8; j++) {
            const uint32_t dOff = (uint32_t)(db + j * 8) * 2;
            uint32_t bh[2], bl[2];
            ldsm2t(sb + SM_YH + ybase + dOff, bh);
            ldsm2t(sb + SM_YL + ybase + dOff, bl);
            mma16816(a2[j], ae, bh);
            mma16816(a2[j], ae, bl);
        }
    }
    __syncthreads();      // Y tiles dead; reuse as PS staging

    // stage fragments to PS[64][PITCHF] f32
    const int r0 = mb + (lane >> 2);
    #pragma unroll
    for (int j = 0; j < 8; j++) {
        const int dc = db + j * 8 + 2 * (lane & 3);
        *(float2*)(smem + SM_PS + ((uint32_t)r0 * PITCHF + dc) * 4) =
            make_float2(a2[j][0], a2[j][1]);
        *(float2*)(smem + SM_PS + ((uint32_t)(r0 + 8) * PITCHF + dc) * 4) =
            make_float2(a2[j][2], a2[j][3]);
    }
    __syncthreads();

    // combine ph + pl rows, coalesced store g_cvec[c][b][d]
    #pragma unroll
    for (int i4 = t; i4 < 1024; i4 += NT) {
        const int b2 = i4 >> 5, d4 = (i4 & 31) * 4;
        float4 pa = *(const float4*)(smem + SM_PS + ((uint32_t)b2 * PITCHF + d4) * 4);
        float4 pb = *(const float4*)(smem + SM_PS + ((uint32_t)(b2 + 32) * PITCHF + d4) * 4);
        float4 o = make_float4(pa.x + pb.x, pa.y + pb.y, pa.z + pb.z, pa.w + pb.w);
        *(float4*)(g_cvec + ((size_t)c * B + b2) * D + d4) = o;
    }
}

// ---------------------------------------------------------------------------
// K2: fused finisher. Grid = B, 512 threads (16 warps).
//  Block-parallel M_b and SE_b; warp w owns chunks [w*16, w*16+16); lane owns
//  d4 = lane*4 (float4, coalesced, MLP 16); smem-reduce 16 partial rows;
//  epilogue.
// ---------------------------------------------------------------------------
__global__ __launch_bounds__(512) void k_final(const float* __restrict__ x,
                                               const float* __restrict__ al,
                                               float* __restrict__ out) {
    __shared__ float sc[NCH];
    __shared__ float ps[16][PITCHF];
    __shared__ float red[16];
    __shared__ float sM, sSE;
    const int t = threadIdx.x, lane = t & 31, w = t >> 5;
    const int b = blockIdx.x;

    float cm0 = 0.f;
    if (t < NCH) {
        cm0 = g_cmax[b * NCH + t];
        float m = cm0;
        #pragma unroll
        for (int o = 16; o > 0; o >>= 1) m = fmaxf(m, __shfl_xor_sync(0xffffffffu, m, o));
        if (lane == 0) red[w] = m;
    }
    __syncthreads();
    if (t == 0) {
        float m = red[0];
        #pragma unroll
        for (int i = 1; i < 8; i++) m = fmaxf(m, red[i]);
        sM = m;
    }
    __syncthreads();
    if (t < NCH) {
        float s = __expf(cm0 - sM);
        sc[t] = s;
        float p = s * g_csum[b * NCH + t];
        #pragma unroll
        for (int o = 16; o > 0; o >>= 1) p += __shfl_xor_sync(0xffffffffu, p, o);
        if (lane == 0) red[w] = p;
    }
    __syncthreads();
    if (t == 0) {
        float s = 0.f;
        #pragma unroll
        for (int i = 0; i < 8; i++) s += red[i];
        sSE = s;
    }
    __syncthreads();

    // v reduction: warp w covers 16 chunks, lane covers 4 d's
    float4 a4 = make_float4(0.f, 0.f, 0.f, 0.f);
    const int d4 = lane * 4;
    #pragma unroll
    for (int j = 0; j < 16; j++) {
        const int cc = w * 16 + j;
        const float4 vv = *(const float4*)(g_cvec + ((size_t)cc * B + b) * D + d4);
        const float s = sc[cc];
        a4.x = fmaf(s, vv.x, a4.x);
        a4.y = fmaf(s, vv.y, a4.y);
        a4.z = fmaf(s, vv.z, a4.z);
        a4.w = fmaf(s, vv.w, a4.w);
    }
    *(float4*)&ps[w][d4] = a4;
    __syncthreads();

    if (t < D) {
        float v = 0.f;
        #pragma unroll
        for (int w2 = 0; w2 < 16; w2++) v += ps[w2][t];
        float a = al[b];
        float var = 1.f - a;
        out[b * D + t] = (x[b * D + t] - sqrtf(a) * (v / sSE)) * rsqrtf(var);
    }
}

extern "C" void kernel_launch(void* const* d_in, const int* in_sizes, int n_in,
                              void* d_out, int out_size) {
    const float* x  = (const float*)d_in[0];
    const float* al = (const float*)d_in[1];
    const float* y  = (const float*)d_in[2];
    float* out = (float*)d_out;

    cudaFuncSetAttribute(k_chunk, cudaFuncAttributeMaxDynamicSharedMemorySize, SMEM_TOTAL);

    k_chunk<<<NCH, NT, SMEM_TOTAL>>>(x, al, y);
    k_final<<<B, 512>>>(x, al, out);
}

// round 13
// speedup vs baseline: 1.4885x; 1.0122x over previous
#include <cuda_runtime.h>
#include <cuda_fp16.h>
#include <math.h>
#include <stdint.h>

#define B 32
#define N 32768
#define D 128
#define CH 128
#define NCH (N / CH)       // 256

#define NT 256
#define PITCH 136          // halves per fp16 tile row (272 B, 16B-aligned)
#define PITCHF 132         // floats per staging row

// smem byte offsets (k_chunk)
#define SM_YH 0            // [128][PITCH] fp16  34816 B
#define SM_YL 34816
#define SM_XT 69632        // [64][PITCH] fp16   17408 B
#define SM_ES 87040        // [64][PITCH] fp16
#define SM_Y2 104448       // float[128]
#define SM_SA 104960       // float[32]
#define SM_SC 105088
#define SM_RED 105216      // float[8][32]
#define SM_CM 106240       // float[32]
#define SM_SSC 106368      // float[32]
#define SM_X2 106496       // float[32]
#define SM_VAR 106624      // float[32]
#define SMEM_TOTAL 106752
#define SM_PS 0            // f32 [64][PITCHF] staging, aliases Y tiles after GEMM2

#define L2E 1.44269504f

// gmem scratch (no allocations allowed)
__device__ float g_cmax[B * NCH];
__device__ float g_csum[B * NCH];
__device__ float g_cvec[NCH * B * D];      // [c][b][d]

__device__ __forceinline__ uint32_t s2u(const void* p) {
    uint32_t a;
    asm("{ .reg .u64 t; cvta.to.shared.u64 t, %1; cvt.u32.u64 %0, t; }" : "=r"(a) : "l"(p));
    return a;
}
__device__ __forceinline__ float ex2f(float x) {
    float y; asm("ex2.approx.f32 %0, %1;" : "=f"(y) : "f"(x)); return y;
}
__device__ __forceinline__ void ldsm4(uint32_t a, uint32_t r[4]) {
    asm volatile("ldmatrix.sync.aligned.m8n8.x4.shared.b16 {%0,%1,%2,%3}, [%4];"
        : "=r"(r[0]), "=r"(r[1]), "=r"(r[2]), "=r"(r[3]) : "r"(a));
}
__device__ __forceinline__ void ldsm2(uint32_t a, uint32_t r[2]) {
    asm volatile("ldmatrix.sync.aligned.m8n8.x2.shared.b16 {%0,%1}, [%2];"
        : "=r"(r[0]), "=r"(r[1]) : "r"(a));
}
__device__ __forceinline__ void ldsm2t(uint32_t a, uint32_t r[2]) {
    asm volatile("ldmatrix.sync.aligned.m8n8.x2.trans.shared.b16 {%0,%1}, [%2];"
        : "=r"(r[0]), "=r"(r[1]) : "r"(a));
}
__device__ __forceinline__ void mma16816(float c[4], const uint32_t a[4], const uint32_t b[2]) {
    asm volatile("mma.sync.aligned.m16n8k16.row.col.f32.f16.f16.f32 "
        "{%0,%1,%2,%3}, {%4,%5,%6,%7}, {%8,%9}, {%0,%1,%2,%3};"
        : "+f"(c[0]), "+f"(c[1]), "+f"(c[2]), "+f"(c[3])
        : "r"(a[0]), "r"(a[1]), "r"(a[2]), "r"(a[3]), "r"(b[0]), "r"(b[1]));
}

// ---------------------------------------------------------------------------
// K1: HMMA chunk kernel with in-CTA prep. Grid NCH, 256 threads = 8 warps.
// (unchanged from R12)
// ---------------------------------------------------------------------------
__global__ __launch_bounds__(NT) void k_chunk(const float* __restrict__ x,
                                              const float* __restrict__ al,
                                              const float* __restrict__ y) {
    extern __shared__ char smem[];
    const uint32_t sb = s2u(smem);
    const int t = threadIdx.x, w = t >> 5, lane = t & 31;
    const int c = blockIdx.x;

    if (t < B) {
        float a = al[t], var = 1.0f - a;
        *(float*)(smem + SM_VAR + t * 4) = var;
        *(float*)(smem + SM_SSC + t * 4) = sqrtf(a) / var;
        *(float*)(smem + SM_SC + t * 4) = 0.5f * a / var;
    }
    __syncthreads();

    // build x~ tile in smem + x2 partials (8 threads per b, 16 k each)
    {
        const int b = t >> 3, kb = (t & 7) * 16;
        const float sc_ = *(const float*)(smem + SM_SSC + b * 4);
        float x2p = 0.f;
        #pragma unroll
        for (int j = 0; j < 16; j++) {
            const int k = kb + j;
            float raw = x[b * D + k];
            x2p = fmaf(raw, raw, x2p);
            float xv = sc_ * raw;
            __half h = __float2half_rn(xv);
            __half lo = __float2half_rn(xv - __half2float(h));
            *(__half*)(smem + SM_XT + ((uint32_t)b * PITCH + k) * 2) = h;
            *(__half*)(smem + SM_XT + ((uint32_t)(b + 32) * PITCH + k) * 2) = lo;
        }
        x2p += __shfl_xor_sync(0xffffffffu, x2p, 1);
        x2p += __shfl_xor_sync(0xffffffffu, x2p, 2);
        x2p += __shfl_xor_sync(0xffffffffu, x2p, 4);
        if ((t & 7) == 0) *(float*)(smem + SM_X2 + b * 4) = x2p;
    }

    // stage y: fp32 -> yh/yl fp16 tiles + y2 per row
    {
        const float4* y4 = (const float4*)(y + (size_t)c * CH * D);
        #pragma unroll
        for (int kk = 0; kk < 16; kk++) {
            const int i = kk * NT + t;
            const int row = i >> 5;
            const int c4 = (i & 31) * 4;
            float4 v = y4[i];
            float sq = fmaf(v.x, v.x, fmaf(v.y, v.y, fmaf(v.z, v.z, v.w * v.w)));
            #pragma unroll
            for (int o = 16; o > 0; o >>= 1) sq += __shfl_xor_sync(0xffffffffu, sq, o);
            if (lane == 0) *(float*)(smem + SM_Y2 + row * 4) = sq;
            __half hx = __float2half_rn(v.x), hy = __float2half_rn(v.y);
            __half hz = __float2half_rn(v.z), hw = __float2half_rn(v.w);
            __half2 h01 = __halves2half2(hx, hy), h23 = __halves2half2(hz, hw);
            __half2 l01 = __halves2half2(__float2half_rn(v.x - __half2float(hx)),
                                         __float2half_rn(v.y - __half2float(hy)));
            __half2 l23 = __halves2half2(__float2half_rn(v.z - __half2float(hz)),
                                         __float2half_rn(v.w - __half2float(hw)));
            const uint32_t off = (uint32_t)(row * PITCH + c4) * 2;
            *(__half2*)(smem + SM_YH + off) = h01;
            *(__half2*)(smem + SM_YH + off + 4) = h23;
            *(__half2*)(smem + SM_YL + off) = l01;
            *(__half2*)(smem + SM_YL + off + 4) = l23;
        }
    }
    __syncthreads();

    if (t < B) {
        float var = *(const float*)(smem + SM_VAR + t * 4);
        float x2 = *(const float*)(smem + SM_X2 + t * 4);
        *(float*)(smem + SM_SA + t * 4) = -(0.5f * (float)D * logf(var) + 0.5f / var * x2);
    }
    __syncthreads();

    // ---- GEMM1 ----
    float acc[8][4];
    #pragma unroll
    for (int j = 0; j < 8; j++)
        #pragma unroll
        for (int q = 0; q < 4; q++) acc[j][q] = 0.f;

    const int nb = w * 16;
    const uint32_t aAddr = sb + SM_YH + (uint32_t)(nb + (lane & 15)) * (PITCH * 2)
                         + (uint32_t)(((lane >> 4) << 3) * 2);
    const uint32_t bAddr = sb + SM_XT + (uint32_t)(lane & 7) * (PITCH * 2)
                         + (uint32_t)((((lane >> 3) & 1) << 3) * 2);
    #pragma unroll
    for (int ks = 0; ks < 8; ks++) {
        const uint32_t kOff = (uint32_t)(ks * 32);
        uint32_t ah[4], alr[4];
        ldsm4(aAddr + kOff, ah);
        ldsm4(aAddr + (SM_YL - SM_YH) + kOff, alr);
        #pragma unroll
        for (int j = 0; j < 8; j++) {
            uint32_t bb[2];
            ldsm2(bAddr + (uint32_t)(j * 8) * (PITCH * 2) + kOff, bb);
            mma16816(acc[j], ah, bb);
            mma16816(acc[j], alr, bb);
        }
    }

    // ---- epilogue 1 ----
    const int n0 = nb + (lane >> 2);
    const float y20 = *(const float*)(smem + SM_Y2 + n0 * 4);
    const float y21 = *(const float*)(smem + SM_Y2 + (n0 + 8) * 4);
    const float* sAs = (const float*)(smem + SM_SA);
    const float* sCs = (const float*)(smem + SM_SC);
    float* red = (float*)(smem + SM_RED);
    float* cmv = (float*)(smem + SM_CM);

    float lv[4][4];
    float mx[4][2];
    #pragma unroll
    for (int j = 0; j < 4; j++) {
        #pragma unroll
        for (int cc = 0; cc < 2; cc++) {
            const int b2 = j * 8 + 2 * (lane & 3) + cc;
            lv[j][cc]     = acc[j][cc]     + acc[j + 4][cc]     + sAs[b2] - sCs[b2] * y20;
            lv[j][cc + 2] = acc[j][cc + 2] + acc[j + 4][cc + 2] + sAs[b2] - sCs[b2] * y21;
            float m = fmaxf(lv[j][cc], lv[j][cc + 2]);
            #pragma unroll
            for (int o = 4; o < 32; o <<= 1) m = fmaxf(m, __shfl_xor_sync(0xffffffffu, m, o));
            mx[j][cc] = m;
        }
    }
    if (lane < 4) {
        #pragma unroll
        for (int j = 0; j < 4; j++)
            #pragma unroll
            for (int cc = 0; cc < 2; cc++)
                red[w * 32 + j * 8 + 2 * lane + cc] = mx[j][cc];
    }
    __syncthreads();
    if (t < 32) {
        float m = -3.4e38f;
        #pragma unroll
        for (int w2 = 0; w2 < 8; w2++) m = fmaxf(m, red[w2 * 32 + t]);
        cmv[t] = m;
        g_cmax[t * NCH + c] = m;
    }
    __syncthreads();

    float sv[4][2];
    #pragma unroll
    for (int j = 0; j < 4; j++) {
        #pragma unroll
        for (int cc = 0; cc < 2; cc++) {
            const int b2 = j * 8 + 2 * (lane & 3) + cc;
            const float cmb = cmv[b2];
            float e0 = ex2f((lv[j][cc] - cmb) * L2E);
            float e1 = ex2f((lv[j][cc + 2] - cmb) * L2E);
            __half h0 = __float2half_rn(e0), h1 = __float2half_rn(e1);
            __half l0 = __float2half_rn(e0 - __half2float(h0));
            __half l1 = __float2half_rn(e1 - __half2float(h1));
            *(__half*)(smem + SM_ES + ((uint32_t)b2 * PITCH + n0) * 2) = h0;
            *(__half*)(smem + SM_ES + ((uint32_t)b2 * PITCH + n0 + 8) * 2) = h1;
            *(__half*)(smem + SM_ES + ((uint32_t)(b2 + 32) * PITCH + n0) * 2) = l0;
            *(__half*)(smem + SM_ES + ((uint32_t)(b2 + 32) * PITCH + n0 + 8) * 2) = l1;
            float s = e0 + e1;
            #pragma unroll
            for (int o = 4; o < 32; o <<= 1) s += __shfl_xor_sync(0xffffffffu, s, o);
            sv[j][cc] = s;
        }
    }
    if (lane < 4) {
        #pragma unroll
        for (int j = 0; j < 4; j++)
            #pragma unroll
            for (int cc = 0; cc < 2; cc++)
                red[w * 32 + j * 8 + 2 * lane + cc] = sv[j][cc];
    }
    __syncthreads();
    if (t < 32) {
        float s = 0.f;
        #pragma unroll
        for (int w2 = 0; w2 < 8; w2++) s += red[w2 * 32 + t];
        g_csum[t * NCH + c] = s;
    }

    // ---- GEMM2 ----
    float a2[8][4];
    #pragma unroll
    for (int j = 0; j < 8; j++)
        #pragma unroll
        for (int q = 0; q < 4; q++) a2[j][q] = 0.f;

    const int mb = (w & 3) * 16;
    const int db = (w >> 2) * 64;
    const uint32_t aeAddr = sb + SM_ES + (uint32_t)(mb + (lane & 15)) * (PITCH * 2)
                          + (uint32_t)(((lane >> 4) << 3) * 2);
    const uint32_t btRow = (uint32_t)(lane & 15) * (PITCH * 2);
    #pragma unroll
    for (int ks = 0; ks < 8; ks++) {
        const uint32_t nOff = (uint32_t)(ks * 16);
        uint32_t ae[4];
        ldsm4(aeAddr + nOff * 2, ae);
        const uint32_t ybase = nOff * (PITCH * 2) + btRow;
        #pragma unroll
        for (int j = 0; j < 8; j++) {
            const uint32_t dOff = (uint32_t)(db + j * 8) * 2;
            uint32_t bh[2], bl[2];
            ldsm2t(sb + SM_YH + ybase + dOff, bh);
            ldsm2t(sb + SM_YL + ybase + dOff, bl);
            mma16816(a2[j], ae, bh);
            mma16816(a2[j], ae, bl);
        }
    }
    __syncthreads();

    const int r0 = mb + (lane >> 2);
    #pragma unroll
    for (int j = 0; j < 8; j++) {
        const int dc = db + j * 8 + 2 * (lane & 3);
        *(float2*)(smem + SM_PS + ((uint32_t)r0 * PITCHF + dc) * 4) =
            make_float2(a2[j][0], a2[j][1]);
        *(float2*)(smem + SM_PS + ((uint32_t)(r0 + 8) * PITCHF + dc) * 4) =
            make_float2(a2[j][2], a2[j][3]);
    }
    __syncthreads();

    #pragma unroll
    for (int i4 = t; i4 < 1024; i4 += NT) {
        const int b2 = i4 >> 5, d4 = (i4 & 31) * 4;
        float4 pa = *(const float4*)(smem + SM_PS + ((uint32_t)b2 * PITCHF + d4) * 4);
        float4 pb = *(const float4*)(smem + SM_PS + ((uint32_t)(b2 + 32) * PITCHF + d4) * 4);
        float4 o = make_float4(pa.x + pb.x, pa.y + pb.y, pa.z + pb.z, pa.w + pb.w);
        *(float4*)(g_cvec + ((size_t)c * B + b2) * D + d4) = o;
    }
}

// ---------------------------------------------------------------------------
// K2: finisher. Grid = B*4 = 128 CTAs, 256 threads (8 warps).
//  CTA (b, dg): redundant block-parallel M_b, SE_b; warp w reduces chunks
//  [32w, 32w+32) for d = dg*32 + lane (coalesced 128B lines, MLP 32);
//  8 partial rows folded in smem; epilogue for 32 outputs.
// ---------------------------------------------------------------------------
__global__ __launch_bounds__(256) void k_final(const float* __restrict__ x,
                                               const float* __restrict__ al,
                                               float* __restrict__ out) {
    __shared__ float sc[NCH];
    __shared__ float red[8];
    __shared__ float ps[8][32];
    __shared__ float sM, sSE;
    const int t = threadIdx.x, lane = t & 31, w = t >> 5;
    const int b = blockIdx.x >> 2;
    const int dg = blockIdx.x & 3;

    // block-parallel M (each thread owns one chunk)
    const float cm0 = g_cmax[b * NCH + t];
    {
        float m = cm0;
        #pragma unroll
        for (int o = 16; o > 0; o >>= 1) m = fmaxf(m, __shfl_xor_sync(0xffffffffu, m, o));
        if (lane == 0) red[w] = m;
    }
    __syncthreads();
    if (t == 0) {
        float m = red[0];
        #pragma unroll
        for (int i = 1; i < 8; i++) m = fmaxf(m, red[i]);
        sM = m;
    }
    __syncthreads();

    // scales + SE
    {
        float s = __expf(cm0 - sM);
        sc[t] = s;
        float p = s * g_csum[b * NCH + t];
        #pragma unroll
        for (int o = 16; o > 0; o >>= 1) p += __shfl_xor_sync(0xffffffffu, p, o);
        if (lane == 0) red[w] = p;
    }
    __syncthreads();
    if (t == 0) {
        float s = 0.f;
        #pragma unroll
        for (int i = 0; i < 8; i++) s += red[i];
        sSE = s;
    }
    __syncthreads();

    // v reduction: warp w -> chunks [32w, 32w+32), lane -> d = dg*32+lane
    const int d = dg * 32 + lane;
    float v = 0.f;
    #pragma unroll
    for (int j = 0; j < 32; j++) {
        const int cc = w * 32 + j;
        v = fmaf(sc[cc], g_cvec[((size_t)cc * B + b) * D + d], v);  // 128B line/warp
    }
    ps[w][lane] = v;
    __syncthreads();

    if (t < 32) {
        float vv = 0.f;
        #pragma unroll
        for (int w2 = 0; w2 < 8; w2++) vv += ps[w2][t];
        const int dd = dg * 32 + t;
        float a = al[b];
        float var = 1.f - a;
        out[b * D + dd] = (x[b * D + dd] - sqrtf(a) * (vv / sSE)) * rsqrtf(var);
    }
}

extern "C" void kernel_launch(void* const* d_in, const int* in_sizes, int n_in,
                              void* d_out, int out_size) {
    const float* x  = (const float*)d_in[0];
    const float* al = (const float*)d_in[1];
    const float* y  = (const float*)d_in[2];
    float* out = (float*)d_out;

    cudaFuncSetAttribute(k_chunk, cudaFuncAttributeMaxDynamicSharedMemorySize, SMEM_TOTAL);

    k_chunk<<<NCH, NT, SMEM_TOTAL>>>(x, al, y);
    k_final<<<B * 4, 256>>>(x, al, out);
}